// round 16
// baseline (speedup 1.0000x reference)
#include <cuda_runtime.h>
#include <cuda_bf16.h>
#include <cstdint>

// NODE forest via mma.sync bf16 (plain compute_103 PTX).
// R16 = R15 (warp-autonomous cp.async pipeline) with issue-count cuts:
//  - bias folded into MMA accumulator init (error +~5e-6, still << TAU)
//  - W fragments paired into u64, conflict-free LDS.64 (stride-17 u64 rows)
//  - STRIPS=8, grid 2048 for smoother wave tail
//
// Numerics: 3-pass bf16 split (Ah*Wh + Ah*Wl + Al*Wh, fp32 accum), total
// error bound ~2.7e-4 << TAU=5e-4; |z|<=TAU recomputed with the exact fp32
// ascending-i FMA chain (bias after), bit = z > 2^-23 (== XLA sigmoid rule).
// Leaf indices bit-identical to reference.

#define THREADS 128
#define STRIPS 8
#define NBLK 2048
#define TAU 5e-4f
#define ZTHR 1.1920928955078125e-7f   // 2^-23

// ---- shared layout (bytes) ----
#define XB_OFF    0          // 4 warps x 2 bufs x [16][68] f32 = 34816
#define XB_WARP   8704
#define XB_BUF    4352
#define WH64_OFF  34816      // u64[48 rows][stride 17], 16 used  = 6528
#define WL64_OFF  41344      // u64[48][17]                        = 6528
#define TBL_OFF   47872      // float2[512] = 4096
#define BS_OFF    51968      // f32[48]
#define SMEM_BYTES 52160

static __device__ __forceinline__ uint32_t smem_u32(const void* p) {
    uint32_t a;
    asm("{ .reg .u64 t; cvta.to.shared.u64 t, %1; cvt.u32.u64 %0, t; }"
        : "=r"(a) : "l"(p));
    return a;
}
static __device__ __forceinline__ uint32_t bf16x2_rn(float hi, float lo) {
    uint32_t r;
    asm("cvt.rn.bf16x2.f32 %0, %1, %2;" : "=r"(r) : "f"(hi), "f"(lo));
    return r;
}
static __device__ __forceinline__ void split2(float vx, float vy,
                                              uint32_t& h, uint32_t& l) {
    h = bf16x2_rn(vy, vx);
    float h0 = __uint_as_float(h << 16);
    float h1 = __uint_as_float(h & 0xffff0000u);
    l = bf16x2_rn(vy - h1, vx - h0);
}
static __device__ __forceinline__ void mma_bf16(float* c, const uint32_t* a,
                                                uint32_t b0, uint32_t b1) {
    asm("mma.sync.aligned.m16n8k16.row.col.f32.bf16.bf16.f32 "
        "{%0,%1,%2,%3}, {%4,%5,%6,%7}, {%8,%9}, {%0,%1,%2,%3};"
        : "+f"(c[0]), "+f"(c[1]), "+f"(c[2]), "+f"(c[3])
        : "r"(a[0]), "r"(a[1]), "r"(a[2]), "r"(a[3]), "r"(b0), "r"(b1));
}
#define CP16(dst, src) \
    asm volatile("cp.async.cg.shared.global [%0], [%1], 16;" \
                 :: "r"(dst), "l"(src) : "memory")
#define CP_COMMIT() asm volatile("cp.async.commit_group;" ::: "memory")
#define CP_WAIT1()  asm volatile("cp.async.wait_group 1;" ::: "memory")
#define CP_WAIT0()  asm volatile("cp.async.wait_group 0;" ::: "memory")

__global__ __launch_bounds__(THREADS, 4)
void node_forest_mma_kernel(const float*  __restrict__ x,      // [B,64]
                            const float*  __restrict__ Wsel,   // [48,64]
                            const float*  __restrict__ bsel,   // [48]
                            const float*  __restrict__ leafv,  // [8,64,2]
                            const float*  __restrict__ fcw,    // [2,16]
                            const float*  __restrict__ fcb,    // [2]
                            float2*       __restrict__ out)    // [B]
{
    extern __shared__ unsigned char smem[];
    unsigned long long* Wh64 = (unsigned long long*)(smem + WH64_OFF);
    unsigned long long* Wl64 = (unsigned long long*)(smem + WL64_OFF);
    float2*   tbl = (float2*)(smem + TBL_OFF);
    float*    bs  = (float*)(smem + BS_OFF);

    const int tid = threadIdx.x;
    const uint32_t sbase = smem_u32(smem);

    // ---- prologue: W hi/lo frag-pairs (u64, row stride 17), table, bias ----
    #pragma unroll
    for (int e = tid; e < 768; e += THREADS) {
        int d = e >> 4, j = e & 15;            // row, frag index (kt*4+tig)
        int kt = j >> 2, tg = j & 3;
        int ip0 = kt * 8 + tg;                 // u32-pair column index
        float2 wp0 = *(const float2*)(Wsel + d * 64 + 2 * ip0);
        float2 wp1 = *(const float2*)(Wsel + d * 64 + 2 * (ip0 + 4));
        uint32_t h0, l0, h1, l1;
        split2(wp0.x, wp0.y, h0, l0);
        split2(wp1.x, wp1.y, h1, l1);
        Wh64[d * 17 + j] = (unsigned long long)h0
                         | ((unsigned long long)h1 << 32);
        Wl64[d * 17 + j] = (unsigned long long)l0
                         | ((unsigned long long)l1 << 32);
    }
    #pragma unroll
    for (int e = tid; e < 512; e += THREADS) {
        int t = e >> 6, leaf = e & 63;
        float l0 = leafv[t * 128 + leaf * 2 + 0];
        float l1 = leafv[t * 128 + leaf * 2 + 1];
        tbl[e] = make_float2(l0 * fcw[t * 2]      + l1 * fcw[t * 2 + 1],
                             l0 * fcw[16 + t * 2] + l1 * fcw[16 + t * 2 + 1]);
    }
    if (tid < 48) bs[tid] = bsel[tid];
    __syncthreads();   // the ONLY CTA barrier

    const int lane = tid & 31, w = tid >> 5;
    const int g = lane >> 2, tig = lane & 3;
    const int t2 = tig * 2;
    const float fb0 = __ldg(&fcb[0]), fb1 = __ldg(&fcb[1]);

    // per-lane bias registers (this lane's 12 columns)
    float bb[12];
    #pragma unroll
    for (int n = 0; n < 6; ++n) {
        bb[n * 2]     = bs[n * 8 + t2];
        bb[n * 2 + 1] = bs[n * 8 + t2 + 1];
    }

    const size_t wbase = ((size_t)blockIdx.x * 4 + w) * STRIPS;
    const uint32_t xbw = sbase + XB_OFF + w * XB_WARP;

    // issue strip 0 into buffer 0
    {
        const float* src = x + (wbase << 10);
        #pragma unroll
        for (int it = 0; it < 8; ++it) {
            int f = lane + it * 32;
            int r = f >> 4, c4 = f & 15;
            CP16(xbw + r * 272 + c4 * 16, src + r * 64 + c4 * 4);
        }
        CP_COMMIT();
    }

    #pragma unroll 1
    for (int ss = 0; ss < STRIPS; ++ss) {
        const size_t gstrip = wbase + ss;

        if (ss + 1 < STRIPS) {
            const float* src = x + ((gstrip + 1) << 10);
            uint32_t dst = xbw + ((ss + 1) & 1) * XB_BUF;
            #pragma unroll
            for (int it = 0; it < 8; ++it) {
                int f = lane + it * 32;
                int r = f >> 4, c4 = f & 15;
                CP16(dst + r * 272 + c4 * 16, src + r * 64 + c4 * 4);
            }
            CP_COMMIT();
            CP_WAIT1();
        } else {
            CP_WAIT0();
        }
        __syncwarp();

        const float* xb = (const float*)(smem + XB_OFF + w * XB_WARP
                                              + (ss & 1) * XB_BUF);

        // acc initialized with bias (folded into TC estimate; see header)
        float acc[6][4];
        #pragma unroll
        for (int n = 0; n < 6; ++n) {
            acc[n][0] = bb[n * 2];     acc[n][1] = bb[n * 2 + 1];
            acc[n][2] = bb[n * 2];     acc[n][3] = bb[n * 2 + 1];
        }

        // ---- mainloop: LDS x, split, HMMA (W frags via LDS.64 pairs) ----
        #pragma unroll
        for (int kt = 0; kt < 4; ++kt) {
            int c0 = kt * 16 + t2;
            float2 p0 = *(const float2*)(xb + g * 68 + c0);
            float2 p1 = *(const float2*)(xb + (g + 8) * 68 + c0);
            float2 p2 = *(const float2*)(xb + g * 68 + c0 + 8);
            float2 p3 = *(const float2*)(xb + (g + 8) * 68 + c0 + 8);
            uint32_t ah[4], al[4];
            split2(p0.x, p0.y, ah[0], al[0]);
            split2(p1.x, p1.y, ah[1], al[1]);
            split2(p2.x, p2.y, ah[2], al[2]);
            split2(p3.x, p3.y, ah[3], al[3]);
            #pragma unroll
            for (int n = 0; n < 6; ++n) {
                int idx = (n * 8 + g) * 17 + kt * 4 + tig;
                unsigned long long bh = Wh64[idx];
                unsigned long long bl = Wl64[idx];
                mma_bf16(acc[n], ah, (uint32_t)bh, (uint32_t)(bh >> 32));
                mma_bf16(acc[n], ah, (uint32_t)bl, (uint32_t)(bl >> 32));
                mma_bf16(acc[n], al, (uint32_t)bh, (uint32_t)(bh >> 32));
            }
        }

        // ---- epilogue: band recompute (rare), two-u32 bit masks ----
        uint32_t mlo[2] = {0u, 0u}, mhi[2] = {0u, 0u};
        #pragma unroll
        for (int half = 0; half < 2; ++half) {
            int row = half * 8 + g;
            #pragma unroll
            for (int n = 0; n < 6; ++n) {
                #pragma unroll
                for (int e = 0; e < 2; ++e) {
                    float z = acc[n][2 * half + e];   // bias already inside
                    if (fabsf(z) <= TAU) {
                        // exact fp32 ascending-i chain (bit-faithful)
                        int col = n * 8 + t2 + e;
                        const float4* xr = (const float4*)(xb + row * 68);
                        const float4* wr = (const float4*)(Wsel + col * 64);
                        float a = 0.f;
                        #pragma unroll 1
                        for (int i4 = 0; i4 < 16; ++i4) {
                            float4 xa = xr[i4];
                            float4 wa = __ldg(wr + i4);
                            a = __fmaf_rn(xa.x, wa.x, a);
                            a = __fmaf_rn(xa.y, wa.y, a);
                            a = __fmaf_rn(xa.z, wa.z, a);
                            a = __fmaf_rn(xa.w, wa.w, a);
                        }
                        z = __fadd_rn(a, bb[n * 2 + e]);
                    }
                    uint32_t bit = (z > ZTHR) ? 1u : 0u;  // == XLA sigmoid rule
                    if (n < 3) mlo[half] |= bit << (n * 8 + t2 + e);
                    else       mhi[half] |= bit << ((n - 3) * 8 + t2 + e);
                }
            }
        }
        #pragma unroll
        for (int half = 0; half < 2; ++half) {
            mlo[half] |= __shfl_xor_sync(0xffffffffu, mlo[half], 1);
            mhi[half] |= __shfl_xor_sync(0xffffffffu, mhi[half], 1);
            mlo[half] |= __shfl_xor_sync(0xffffffffu, mlo[half], 2);
            mhi[half] |= __shfl_xor_sync(0xffffffffu, mhi[half], 2);
        }

        // distributed leaf gather: lane tig -> half = tig&1, trees grp*4..+3
        {
            const int h = tig & 1, grp = tig >> 1;
            uint32_t m = grp ? mhi[h] : mlo[h];
            float o0 = 0.f, o1 = 0.f;
            #pragma unroll
            for (int t = 0; t < 4; ++t) {
                int bits6 = (int)(m >> (6 * t)) & 63;
                int leaf = __brev((unsigned)bits6) >> 26;
                float2 tv = tbl[(grp * 4 + t) * 64 + leaf];
                o0 += tv.x;
                o1 += tv.y;
            }
            o0 += __shfl_xor_sync(0xffffffffu, o0, 2);
            o1 += __shfl_xor_sync(0xffffffffu, o1, 2);
            if (tig < 2)
                out[gstrip * 16 + tig * 8 + g] = make_float2(o0 + fb0,
                                                             o1 + fb1);
        }
        __syncwarp();   // xb fully consumed before next cp.async overwrite
    }
}

extern "C" void kernel_launch(void* const* d_in, const int* in_sizes, int n_in,
                              void* d_out, int out_size) {
    (void)in_sizes; (void)n_in; (void)out_size;
    cudaFuncSetAttribute(node_forest_mma_kernel,
                         cudaFuncAttributeMaxDynamicSharedMemorySize, SMEM_BYTES);
    cudaFuncSetAttribute(node_forest_mma_kernel,
                         cudaFuncAttributePreferredSharedMemoryCarveout, 100);
    node_forest_mma_kernel<<<NBLK, THREADS, SMEM_BYTES>>>(
        (const float*)d_in[0],   // x
        (const float*)d_in[1],   // W_sel
        (const float*)d_in[2],   // b_sel
        (const float*)d_in[3],   // leaf_values
        (const float*)d_in[4],   // fc_w
        (const float*)d_in[5],   // fc_b
        (float2*)d_out);
}

// round 17
// speedup vs baseline: 1.4913x; 1.4913x over previous
#include <cuda_runtime.h>
#include <cuda_bf16.h>
#include <cstdint>

// NODE forest via mma.sync bf16 (plain compute_103 PTX).
// R17 = R15 (best: 104.9us) + the two independently-safe R16 changes:
//  - bias folded into MMA accumulator init (error +~5e-6 << TAU)
//  - STRIPS=8 / grid 2048 (finer wave tail)
// R16's paired-W LDS.64 is REVERTED: its stride-17-u64 layout had
// bank = 2g+2tig (collisions) -> L1 80%, 147us. R15's u32 layout is a
// perfect 0..31 bank permutation (bank = 4g+tig).
//
// Numerics: 3-pass bf16 split (Ah*Wh + Ah*Wl + Al*Wh, fp32 accum), total
// error bound ~2.7e-4 << TAU=5e-4; |z|<=TAU recomputed with the exact fp32
// ascending-i FMA chain (bias after), bit = z > 2^-23 (== XLA sigmoid rule).
// Leaf indices bit-identical to reference.

#define THREADS 128
#define STRIPS 8
#define NBLK 2048
#define TAU 5e-4f
#define ZTHR 1.1920928955078125e-7f   // 2^-23

// ---- shared layout (bytes) ----
#define XB_OFF   0          // 4 warps x 2 bufs x [16][68] f32 = 34816
#define XB_WARP  8704
#define XB_BUF   4352
#define WHP_OFF  34816      // u32[48][36] = 6912  (bank = 4g+tig, perfect)
#define WLP_OFF  41728      // u32[48][36] = 6912
#define TBL_OFF  48640      // float2[512] = 4096
#define BS_OFF   52736      // f32[48]
#define SMEM_BYTES 52928

static __device__ __forceinline__ uint32_t smem_u32(const void* p) {
    uint32_t a;
    asm("{ .reg .u64 t; cvta.to.shared.u64 t, %1; cvt.u32.u64 %0, t; }"
        : "=r"(a) : "l"(p));
    return a;
}
static __device__ __forceinline__ uint32_t bf16x2_rn(float hi, float lo) {
    uint32_t r;
    asm("cvt.rn.bf16x2.f32 %0, %1, %2;" : "=r"(r) : "f"(hi), "f"(lo));
    return r;
}
static __device__ __forceinline__ void split2(float vx, float vy,
                                              uint32_t& h, uint32_t& l) {
    h = bf16x2_rn(vy, vx);
    float h0 = __uint_as_float(h << 16);
    float h1 = __uint_as_float(h & 0xffff0000u);
    l = bf16x2_rn(vy - h1, vx - h0);
}
static __device__ __forceinline__ void mma_bf16(float* c, const uint32_t* a,
                                                const uint32_t* b) {
    asm("mma.sync.aligned.m16n8k16.row.col.f32.bf16.bf16.f32 "
        "{%0,%1,%2,%3}, {%4,%5,%6,%7}, {%8,%9}, {%0,%1,%2,%3};"
        : "+f"(c[0]), "+f"(c[1]), "+f"(c[2]), "+f"(c[3])
        : "r"(a[0]), "r"(a[1]), "r"(a[2]), "r"(a[3]), "r"(b[0]), "r"(b[1]));
}
#define CP16(dst, src) \
    asm volatile("cp.async.cg.shared.global [%0], [%1], 16;" \
                 :: "r"(dst), "l"(src) : "memory")
#define CP_COMMIT() asm volatile("cp.async.commit_group;" ::: "memory")
#define CP_WAIT1()  asm volatile("cp.async.wait_group 1;" ::: "memory")
#define CP_WAIT0()  asm volatile("cp.async.wait_group 0;" ::: "memory")

__global__ __launch_bounds__(THREADS, 4)
void node_forest_mma_kernel(const float*  __restrict__ x,      // [B,64]
                            const float*  __restrict__ Wsel,   // [48,64]
                            const float*  __restrict__ bsel,   // [48]
                            const float*  __restrict__ leafv,  // [8,64,2]
                            const float*  __restrict__ fcw,    // [2,16]
                            const float*  __restrict__ fcb,    // [2]
                            float2*       __restrict__ out)    // [B]
{
    extern __shared__ unsigned char smem[];
    uint32_t* Whp = (uint32_t*)(smem + WHP_OFF);
    uint32_t* Wlp = (uint32_t*)(smem + WLP_OFF);
    float2*   tbl = (float2*)(smem + TBL_OFF);
    float*    bs  = (float*)(smem + BS_OFF);

    const int tid = threadIdx.x;
    const uint32_t sbase = smem_u32(smem);

    // ---- prologue (once per CTA): W hi/lo tiles, table fold, bias ----
    #pragma unroll
    for (int e = tid; e < 1536; e += THREADS) {
        int d = e >> 5, ip = e & 31;
        float2 wp = *(const float2*)(Wsel + d * 64 + 2 * ip);
        uint32_t h, l;
        split2(wp.x, wp.y, h, l);
        Whp[d * 36 + ip] = h;
        Wlp[d * 36 + ip] = l;
    }
    #pragma unroll
    for (int e = tid; e < 512; e += THREADS) {
        int t = e >> 6, leaf = e & 63;
        float l0 = leafv[t * 128 + leaf * 2 + 0];
        float l1 = leafv[t * 128 + leaf * 2 + 1];
        tbl[e] = make_float2(l0 * fcw[t * 2]      + l1 * fcw[t * 2 + 1],
                             l0 * fcw[16 + t * 2] + l1 * fcw[16 + t * 2 + 1]);
    }
    if (tid < 48) bs[tid] = bsel[tid];
    __syncthreads();   // the ONLY CTA barrier

    const int lane = tid & 31, w = tid >> 5;
    const int g = lane >> 2, tig = lane & 3;
    const int t2 = tig * 2;
    const float fb0 = __ldg(&fcb[0]), fb1 = __ldg(&fcb[1]);

    // bias for this lane's 12 columns, held in registers
    float bb[12];
    #pragma unroll
    for (int n = 0; n < 6; ++n) {
        bb[n * 2]     = bs[n * 8 + t2];
        bb[n * 2 + 1] = bs[n * 8 + t2 + 1];
    }

    const size_t wbase = ((size_t)blockIdx.x * 4 + w) * STRIPS;
    const uint32_t xbw = sbase + XB_OFF + w * XB_WARP;

    // issue strip 0 into buffer 0
    {
        const float* src = x + (wbase << 10);
        #pragma unroll
        for (int it = 0; it < 8; ++it) {
            int f = lane + it * 32;
            int r = f >> 4, c4 = f & 15;
            CP16(xbw + r * 272 + c4 * 16, src + r * 64 + c4 * 4);
        }
        CP_COMMIT();
    }

    #pragma unroll 1
    for (int ss = 0; ss < STRIPS; ++ss) {
        const size_t gstrip = wbase + ss;

        if (ss + 1 < STRIPS) {
            const float* src = x + ((gstrip + 1) << 10);
            uint32_t dst = xbw + ((ss + 1) & 1) * XB_BUF;
            #pragma unroll
            for (int it = 0; it < 8; ++it) {
                int f = lane + it * 32;
                int r = f >> 4, c4 = f & 15;
                CP16(dst + r * 272 + c4 * 16, src + r * 64 + c4 * 4);
            }
            CP_COMMIT();
            CP_WAIT1();
        } else {
            CP_WAIT0();
        }
        __syncwarp();

        const float* xb = (const float*)(smem + XB_OFF + w * XB_WARP
                                              + (ss & 1) * XB_BUF);

        // acc initialized with bias (folded into the TC estimate)
        float acc[6][4];
        #pragma unroll
        for (int n = 0; n < 6; ++n) {
            acc[n][0] = bb[n * 2];     acc[n][1] = bb[n * 2 + 1];
            acc[n][2] = bb[n * 2];     acc[n][3] = bb[n * 2 + 1];
        }

        // ---- mainloop: LDS x, split, HMMA (R15's conflict-free W loads) ----
        #pragma unroll
        for (int kt = 0; kt < 4; ++kt) {
            uint32_t bh[6][2], bl[6][2];
            #pragma unroll
            for (int n = 0; n < 6; ++n) {
                int ip0 = (n * 8 + g) * 36 + kt * 8 + tig;
                bh[n][0] = Whp[ip0];  bh[n][1] = Whp[ip0 + 4];
                bl[n][0] = Wlp[ip0];  bl[n][1] = Wlp[ip0 + 4];
            }
            int c0 = kt * 16 + t2;
            float2 p0 = *(const float2*)(xb + g * 68 + c0);
            float2 p1 = *(const float2*)(xb + (g + 8) * 68 + c0);
            float2 p2 = *(const float2*)(xb + g * 68 + c0 + 8);
            float2 p3 = *(const float2*)(xb + (g + 8) * 68 + c0 + 8);
            uint32_t ah[4], al[4];
            split2(p0.x, p0.y, ah[0], al[0]);
            split2(p1.x, p1.y, ah[1], al[1]);
            split2(p2.x, p2.y, ah[2], al[2]);
            split2(p3.x, p3.y, ah[3], al[3]);
            #pragma unroll
            for (int n = 0; n < 6; ++n) {
                mma_bf16(acc[n], ah, bh[n]);
                mma_bf16(acc[n], ah, bl[n]);
                mma_bf16(acc[n], al, bh[n]);
            }
        }

        // ---- epilogue: band recompute (rare), two-u32 bit masks ----
        uint32_t mlo[2] = {0u, 0u}, mhi[2] = {0u, 0u};
        #pragma unroll
        for (int half = 0; half < 2; ++half) {
            int row = half * 8 + g;
            #pragma unroll
            for (int n = 0; n < 6; ++n) {
                #pragma unroll
                for (int e = 0; e < 2; ++e) {
                    float z = acc[n][2 * half + e];   // bias already inside
                    if (fabsf(z) <= TAU) {
                        // exact fp32 ascending-i chain (bit-faithful)
                        int col = n * 8 + t2 + e;
                        const float4* xr = (const float4*)(xb + row * 68);
                        const float4* wr = (const float4*)(Wsel + col * 64);
                        float a = 0.f;
                        #pragma unroll 1
                        for (int i4 = 0; i4 < 16; ++i4) {
                            float4 xa = xr[i4];
                            float4 wa = __ldg(wr + i4);
                            a = __fmaf_rn(xa.x, wa.x, a);
                            a = __fmaf_rn(xa.y, wa.y, a);
                            a = __fmaf_rn(xa.z, wa.z, a);
                            a = __fmaf_rn(xa.w, wa.w, a);
                        }
                        z = __fadd_rn(a, bb[n * 2 + e]);
                    }
                    uint32_t bit = (z > ZTHR) ? 1u : 0u;  // == XLA sigmoid rule
                    if (n < 3) mlo[half] |= bit << (n * 8 + t2 + e);
                    else       mhi[half] |= bit << ((n - 3) * 8 + t2 + e);
                }
            }
        }
        #pragma unroll
        for (int half = 0; half < 2; ++half) {
            mlo[half] |= __shfl_xor_sync(0xffffffffu, mlo[half], 1);
            mhi[half] |= __shfl_xor_sync(0xffffffffu, mhi[half], 1);
            mlo[half] |= __shfl_xor_sync(0xffffffffu, mlo[half], 2);
            mhi[half] |= __shfl_xor_sync(0xffffffffu, mhi[half], 2);
        }

        // distributed leaf gather: lane tig -> half = tig&1, trees grp*4..+3
        {
            const int h = tig & 1, grp = tig >> 1;
            uint32_t m = grp ? mhi[h] : mlo[h];
            float o0 = 0.f, o1 = 0.f;
            #pragma unroll
            for (int t = 0; t < 4; ++t) {
                int bits6 = (int)(m >> (6 * t)) & 63;
                int leaf = __brev((unsigned)bits6) >> 26;
                float2 tv = tbl[(grp * 4 + t) * 64 + leaf];
                o0 += tv.x;
                o1 += tv.y;
            }
            o0 += __shfl_xor_sync(0xffffffffu, o0, 2);
            o1 += __shfl_xor_sync(0xffffffffu, o1, 2);
            if (tig < 2)
                out[gstrip * 16 + tig * 8 + g] = make_float2(o0 + fb0,
                                                             o1 + fb1);
        }
        __syncwarp();   // xb fully consumed before next cp.async overwrite
    }
}

extern "C" void kernel_launch(void* const* d_in, const int* in_sizes, int n_in,
                              void* d_out, int out_size) {
    (void)in_sizes; (void)n_in; (void)out_size;
    cudaFuncSetAttribute(node_forest_mma_kernel,
                         cudaFuncAttributeMaxDynamicSharedMemorySize, SMEM_BYTES);
    cudaFuncSetAttribute(node_forest_mma_kernel,
                         cudaFuncAttributePreferredSharedMemoryCarveout, 100);
    node_forest_mma_kernel<<<NBLK, THREADS, SMEM_BYTES>>>(
        (const float*)d_in[0],   // x
        (const float*)d_in[1],   // W_sel
        (const float*)d_in[2],   // b_sel
        (const float*)d_in[3],   // leaf_values
        (const float*)d_in[4],   // fc_w
        (const float*)d_in[5],   // fc_b
        (float2*)d_out);
}